// round 16
// baseline (speedup 1.0000x reference)
#include <cuda_runtime.h>
#include <math.h>
#include <stdint.h>

#define NROWS 100352

__device__ float g_q[(size_t)24576*1568];   // [B*H, 49, 32], pre-scaled, tf32-rounded
__device__ float g_k[(size_t)24576*1568];
__device__ float g_v[(size_t)24576*1568];
__device__ float g_att[(size_t)NROWS*384];  // tf32-rounded
__device__ float g_hid[(size_t)NROWS*384];  // tf32-rounded hidden
__device__ float g_wq[1152*384];            // tf32-rounded w_qkv
__device__ float g_wo[384*384];             // tf32-rounded w_out
__device__ int   g_pack[2401];              // (i*60+j)<<16 | ridx*12

__device__ __forceinline__ uint32_t smem_u32(const void* p) {
    uint32_t a;
    asm("{ .reg .u64 t; cvta.to.shared.u64 t, %1; cvt.u32.u64 %0, t; }" : "=r"(a) : "l"(p));
    return a;
}
__device__ __forceinline__ uint32_t f2tf(float x) {
    uint32_t r; asm("cvt.rna.tf32.f32 %0, %1;" : "=r"(r) : "f"(x)); return r;
}
__device__ __forceinline__ float tf32f(float x) { return __uint_as_float(f2tf(x)); }
__device__ __forceinline__ void mma8(float* c, const uint32_t* a, uint32_t b0, uint32_t b1) {
    asm volatile("mma.sync.aligned.m16n8k8.row.col.f32.tf32.tf32.f32 "
        "{%0,%1,%2,%3}, {%4,%5,%6,%7}, {%8,%9}, {%0,%1,%2,%3};"
        : "+f"(c[0]), "+f"(c[1]), "+f"(c[2]), "+f"(c[3])
        : "r"(a[0]), "r"(a[1]), "r"(a[2]), "r"(a[3]), "r"(b0), "r"(b1));
}
__device__ __forceinline__ void ldsm4(uint32_t* r, uint32_t a) {
    asm volatile("ldmatrix.sync.aligned.m8n8.x4.shared.b16 {%0,%1,%2,%3}, [%4];"
        : "=r"(r[0]), "=r"(r[1]), "=r"(r[2]), "=r"(r[3]) : "r"(a));
}
__device__ __forceinline__ void ldsm2(uint32_t* r, uint32_t a) {
    asm volatile("ldmatrix.sync.aligned.m8n8.x2.shared.b16 {%0,%1}, [%2];"
        : "=r"(r[0]), "=r"(r[1]) : "r"(a));
}
__device__ __forceinline__ void cp16(uint32_t s, const float* g) {
    asm volatile("cp.async.cg.shared.global [%0], [%1], 16;" :: "r"(s), "l"(g));
}

// ---------------------------------------------------------------------------
// Single prep kernel: tf32-round hidden / w_qkv / w_out + build pack table.
// ---------------------------------------------------------------------------
#define NH4 9633792   // NROWS*384/4
#define NQ4 110592    // 1152*384/4
#define NO4 36864     // 384*384/4

__global__ void prep_kernel(const float4* __restrict__ hid, const float4* __restrict__ wq,
                            const float4* __restrict__ wo, float4* __restrict__ dh,
                            float4* __restrict__ dwq, float4* __restrict__ dwo)
{
    int i = blockIdx.x * blockDim.x + threadIdx.x;
    const float4* s; float4* d; int k;
    if (i < NH4)            { s = hid; d = dh;  k = i; }
    else if (i < NH4 + NQ4) { s = wq;  d = dwq; k = i - NH4; }
    else if (i < NH4 + NQ4 + NO4) { s = wo; d = dwo; k = i - NH4 - NQ4; }
    else return;
    float4 v = s[k];
    v.x = tf32f(v.x); v.y = tf32f(v.y); v.z = tf32f(v.z); v.w = tf32f(v.w);
    d[k] = v;
    if (i < 2401) {
        int r = i / 49, j = i - r * 49;
        int yi = r / 7, xi = r - yi * 7, yj = j / 7, xj = j - yj * 7;
        int ridx = (yi - yj + 6) * 13 + (xi - xj + 6);
        g_pack[i] = ((r * 60 + j) << 16) | (ridx * 12);
    }
}

// ===========================================================================
// TF32 GEMM: C[64x128] of A[M,384] @ W[N,384]^T; inputs pre-rounded.
// 8 warps (2m x 4n), each 32x32 output (acc 32 regs) -> 3 CTAs/SM.
// (unchanged from R12/R15)
// ===========================================================================
__device__ __forceinline__ void gemm_tf32(const float* __restrict__ A,
                                          const float* __restrict__ W,
                                          int bm, int bn, float acc[2][4][4])
{
    extern __shared__ float sm[];
    const int tid = threadIdx.x;
    const int l = tid & 31, l7 = l & 7;
    const int wm = (tid >> 5) >> 2, wn = (tid >> 5) & 3;

    const int rA0 = tid >> 3, c4 = tid & 7;
    const float* gaA0 = A + (size_t)(bm + rA0) * 384 + c4 * 4;
    const float* gaA1 = gaA0 + (size_t)32 * 384;
    const float* gbB0 = W + (size_t)(bn + rA0) * 384 + c4 * 4;
    const float* gbB1 = gbB0 + (size_t)32 * 384;
    const float* gbB2 = gbB0 + (size_t)64 * 384;
    const float* gbB3 = gbB0 + (size_t)96 * 384;
    const uint32_t smbase = smem_u32(sm);
    const uint32_t sw = (uint32_t)(((c4 ^ rA0) & 7) << 4);
    const uint32_t sAr0 = smbase + (uint32_t)(rA0 * 128) + sw;
    const uint32_t sAr1 = sAr0 + 32 * 128;
    const uint32_t sBr0 = smbase + 24576 + (uint32_t)(rA0 * 128) + sw;
    const uint32_t sBr1 = sBr0 + 32 * 128;
    const uint32_t sBr2 = sBr0 + 64 * 128;
    const uint32_t sBr3 = sBr0 + 96 * 128;

#pragma unroll
    for (int mi = 0; mi < 2; mi++)
#pragma unroll
        for (int nj = 0; nj < 4; nj++)
#pragma unroll
            for (int q = 0; q < 4; q++) acc[mi][nj][q] = 0.f;

#define ISSUE(KT) do {                                                        \
    uint32_t oa = (uint32_t)((KT) % 3) * 8192;                                \
    uint32_t ob = (uint32_t)((KT) % 3) * 16384;                               \
    int ko = (KT) * 32;                                                       \
    cp16(sAr0 + oa, gaA0 + ko);  cp16(sAr1 + oa, gaA1 + ko);                  \
    cp16(sBr0 + ob, gbB0 + ko);  cp16(sBr1 + ob, gbB1 + ko);                  \
    cp16(sBr2 + ob, gbB2 + ko);  cp16(sBr3 + ob, gbB3 + ko);                  \
    asm volatile("cp.async.commit_group;" ::: "memory");                      \
} while (0)

    ISSUE(0); ISSUE(1);

    const int ah = (l >> 3) & 1, bh2 = l >> 4;
    uint32_t a_rb[2], b_rb[2];
#pragma unroll
    for (int mi = 0; mi < 2; mi++)
        a_rb[mi] = (uint32_t)((wm * 32 + mi * 16 + l7 + ah * 8) * 128);
#pragma unroll
    for (int p = 0; p < 2; p++)
        b_rb[p] = (uint32_t)((wn * 32 + p * 16 + l7 + bh2 * 8) * 128);

    for (int kt = 0; kt < 12; kt++) {
        if (kt < 11) asm volatile("cp.async.wait_group 1;" ::: "memory");
        else         asm volatile("cp.async.wait_group 0;" ::: "memory");
        __syncthreads();
        if (kt < 10) ISSUE(kt + 2);

        const uint32_t bA = smbase + (uint32_t)(kt % 3) * 8192;
        const uint32_t bB = smbase + 24576 + (uint32_t)(kt % 3) * 16384;
#pragma unroll
        for (int kc = 0; kc < 4; kc++) {
            const uint32_t uA = (uint32_t)(((2 * kc + bh2) ^ l7) << 4);
            const uint32_t uB = (uint32_t)(((2 * kc + ah) ^ l7) << 4);
            uint32_t af0[4], af1[4], b0[4], b1[4];
            ldsm4(af0, bA + a_rb[0] + uA);
            ldsm4(af1, bA + a_rb[1] + uA);
            ldsm4(b0, bB + b_rb[0] + uB);
            ldsm4(b1, bB + b_rb[1] + uB);
            mma8(acc[0][0], af0, b0[0], b0[1]);
            mma8(acc[0][1], af0, b0[2], b0[3]);
            mma8(acc[0][2], af0, b1[0], b1[1]);
            mma8(acc[0][3], af0, b1[2], b1[3]);
            mma8(acc[1][0], af1, b0[0], b0[1]);
            mma8(acc[1][1], af1, b0[2], b0[3]);
            mma8(acc[1][2], af1, b1[0], b1[1]);
            mma8(acc[1][3], af1, b1[2], b1[3]);
        }
    }
#undef ISSUE
}

// ---------------------------------------------------------------------------
__global__ void __launch_bounds__(256, 3)
mma_qkv_kernel(const float* __restrict__ bias, int bmoff)
{
    int tid = threadIdx.x;
    int bm = bmoff + blockIdx.y * 64, bn = blockIdx.x * 128;
    float acc[2][4][4];
    gemm_tf32(g_hid, g_wq, bm, bn, acc);

    int l = tid & 31;
    int wm = (tid >> 5) >> 2, wn = (tid >> 5) & 3;
    int part = bn / 384;
    int h = ((bn % 384) + wn * 32) >> 5;
    const float scl = (part == 0) ? 0.17677669529663687f : 1.0f;
    float* base = (part == 0) ? g_q : (part == 1) ? g_k : g_v;

#pragma unroll
    for (int mi = 0; mi < 2; mi++)
#pragma unroll
        for (int nj = 0; nj < 4; nj++) {
            int n = bn + wn * 32 + nj * 8 + (l & 3) * 2;
            int d = nj * 8 + (l & 3) * 2;
            float b0 = bias[n], b1 = bias[n + 1];
#pragma unroll
            for (int rh = 0; rh < 2; rh++) {
                int row = bm + wm * 32 + mi * 16 + (l >> 2) + rh * 8;
                int bb = row / 49, ss = row - bb * 49;
                size_t o = (((size_t)(bb * 12 + h) * 49 + ss) << 5) + d;
                *(float2*)&base[o] =
                    make_float2(tf32f((acc[mi][nj][rh*2] + b0) * scl),
                                tf32f((acc[mi][nj][rh*2+1] + b1) * scl));
            }
        }
}

// ---------------------------------------------------------------------------
__global__ void __launch_bounds__(256, 3)
mma_out_kernel(const float* __restrict__ bias, float* __restrict__ C, int bmoff)
{
    int tid = threadIdx.x;
    int bm = bmoff + blockIdx.y * 64, bn = blockIdx.x * 128;
    float acc[2][4][4];
    gemm_tf32(g_att, g_wo, bm, bn, acc);

    int l = tid & 31;
    int wm = (tid >> 5) >> 2, wn = (tid >> 5) & 3;
#pragma unroll
    for (int mi = 0; mi < 2; mi++)
#pragma unroll
        for (int nj = 0; nj < 4; nj++) {
            int n = bn + wn * 32 + nj * 8 + (l & 3) * 2;
            float b0 = bias[n], b1 = bias[n + 1];
#pragma unroll
            for (int rh = 0; rh < 2; rh++) {
                int row = bm + wm * 32 + mi * 16 + (l >> 2) + rh * 8;
                *(float2*)&C[(size_t)row * 384 + n] =
                    make_float2(acc[mi][nj][rh*2] + b0, acc[mi][nj][rh*2+1] + b1);
            }
        }
}

// ---------------------------------------------------------------------------
// Attention: one CTA per (b,h). Q/K/P frags via ldmatrix; V transposed in
// smem. (math unchanged from R15; bh offset added)
// ---------------------------------------------------------------------------
__global__ void __launch_bounds__(128)
attn_kernel(const float* __restrict__ mask, const float* __restrict__ table, int bhoff)
{
    __shared__ float qs[64 * 36];
    __shared__ float ks[56 * 36];
    __shared__ float vt[32 * 60];   // V transposed: [d][j], j 49..55 zeroed
    __shared__ float amb[64 * 60];  // bias+mask, then P (tf32-rounded)

    int bh = bhoff + blockIdx.x;
    int b = bh / 12, h = bh - b * 12;
    int tid = threadIdx.x, w = tid >> 5, l = tid & 31, g = l >> 2, t = l & 3;
    const int l7 = l & 7, ah = (l >> 3) & 1, bh2 = l >> 4;

    for (int e = tid; e < 224; e += 128) {
        int d = e & 31, jz = 49 + (e >> 5);
        vt[d * 60 + jz] = 0.f;
    }
    const float4* qg = (const float4*)(g_q + (size_t)bh * 1568);
    const float4* kg = (const float4*)(g_k + (size_t)bh * 1568);
    const float4* vg = (const float4*)(g_v + (size_t)bh * 1568);
    for (int e = tid; e < 392; e += 128) {
        int i = e >> 3, c = (e & 7) * 4;
        *(float4*)&qs[i * 36 + c] = qg[e];
        *(float4*)&ks[i * 36 + c] = kg[e];
        float4 vv = vg[e];
        vt[(c + 0) * 60 + i] = vv.x;
        vt[(c + 1) * 60 + i] = vv.y;
        vt[(c + 2) * 60 + i] = vv.z;
        vt[(c + 3) * 60 + i] = vv.w;
    }
    const float* mrow = mask + (size_t)b * 2401;
    for (int e = tid; e < 2401; e += 128) {
        int pk = g_pack[e];
        amb[pk >> 16] = mrow[e] + table[(pk & 0xFFFF) + h];
    }
    __syncthreads();

    const uint32_t qsb = smem_u32(qs), ksb = smem_u32(ks);
    const uint32_t vtb = smem_u32(vt), ambb = smem_u32(amb);
    const uint32_t qrow = (uint32_t)((w * 16 + l7 + ah * 8) * 144);
    uint32_t krow[3];
#pragma unroll
    for (int p = 0; p < 3; p++)
        krow[p] = (uint32_t)((p * 16 + l7 + bh2 * 8) * 144);
    const uint32_t krow6 = (uint32_t)((48 + l7) * 144);
    uint32_t vrow[2];
#pragma unroll
    for (int p = 0; p < 2; p++)
        vrow[p] = (uint32_t)((p * 16 + l7 + bh2 * 8) * 240);

    // QK^T
    float s[7][4];
#pragma unroll
    for (int T = 0; T < 7; T++) { s[T][0]=0.f; s[T][1]=0.f; s[T][2]=0.f; s[T][3]=0.f; }
    const int rA = w * 16 + g;
#pragma unroll
    for (int kc = 0; kc < 4; kc++) {
        uint32_t a[4];
        ldsm4(a, qsb + qrow + (uint32_t)((2 * kc + bh2) << 4));
        uint32_t uB = (uint32_t)((2 * kc + ah) << 4);
#pragma unroll
        for (int p = 0; p < 3; p++) {
            uint32_t kb[4];
            ldsm4(kb, ksb + krow[p] + uB);
            mma8(s[2*p],   a, kb[0], kb[1]);
            mma8(s[2*p+1], a, kb[2], kb[3]);
        }
        uint32_t k2[2];
        ldsm2(k2, ksb + krow6 + uB);
        mma8(s[6], a, k2[0], k2[1]);
    }
#pragma unroll
    for (int T = 0; T < 7; T++) {
        int j0 = T * 8 + 2 * t;
        float2 m0 = *(const float2*)&amb[rA * 60 + j0];
        float2 m1 = *(const float2*)&amb[(rA + 8) * 60 + j0];
        s[T][0] = (j0 < 49)     ? s[T][0] + m0.x : -1e30f;
        s[T][1] = (j0 + 1 < 49) ? s[T][1] + m0.y : -1e30f;
        s[T][2] = (j0 < 49)     ? s[T][2] + m1.x : -1e30f;
        s[T][3] = (j0 + 1 < 49) ? s[T][3] + m1.y : -1e30f;
    }
    float mA = -1e30f, mB = -1e30f;
#pragma unroll
    for (int T = 0; T < 7; T++) {
        mA = fmaxf(mA, fmaxf(s[T][0], s[T][1]));
        mB = fmaxf(mB, fmaxf(s[T][2], s[T][3]));
    }
    mA = fmaxf(mA, __shfl_xor_sync(~0u, mA, 1)); mA = fmaxf(mA, __shfl_xor_sync(~0u, mA, 2));
    mB = fmaxf(mB, __shfl_xor_sync(~0u, mB, 1)); mB = fmaxf(mB, __shfl_xor_sync(~0u, mB, 2));
    float dA = 0.f, dB = 0.f;
#pragma unroll
    for (int T = 0; T < 7; T++) {
        s[T][0] = __expf(s[T][0] - mA); s[T][1] = __expf(s[T][1] - mA);
        s[T][2] = __expf(s[T][2] - mB); s[T][3] = __expf(s[T][3] - mB);
        dA += s[T][0] + s[T][1]; dB += s[T][2] + s[T][3];
    }
    dA += __shfl_xor_sync(~0u, dA, 1); dA += __shfl_xor_sync(~0u, dA, 2);
    dB += __shfl_xor_sync(~0u, dB, 1); dB += __shfl_xor_sync(~0u, dB, 2);
    float iA = 1.f / dA, iB = 1.f / dB;
#pragma unroll
    for (int T = 0; T < 7; T++) {
        int j0 = T * 8 + 2 * t;
        *(float2*)&amb[rA * 60 + j0] =
            make_float2(tf32f(s[T][0] * iA), tf32f(s[T][1] * iA));
        *(float2*)&amb[(rA + 8) * 60 + j0] =
            make_float2(tf32f(s[T][2] * iB), tf32f(s[T][3] * iB));
    }
    __syncwarp();

    // PV
    const uint32_t prow = (uint32_t)((w * 16 + l7 + ah * 8) * 240);
    float o[4][4];
#pragma unroll
    for (int nj = 0; nj < 4; nj++) { o[nj][0]=0.f; o[nj][1]=0.f; o[nj][2]=0.f; o[nj][3]=0.f; }
#pragma unroll
    for (int kc = 0; kc < 7; kc++) {
        uint32_t a[4];
        ldsm4(a, ambb + prow + (uint32_t)((2 * kc + bh2) << 4));
        uint32_t uV = (uint32_t)((2 * kc + ah) << 4);
        uint32_t v0[4], v1[4];
        ldsm4(v0, vtb + vrow[0] + uV);
        ldsm4(v1, vtb + vrow[1] + uV);
        mma8(o[0], a, v0[0], v0[1]);
        mma8(o[1], a, v0[2], v0[3]);
        mma8(o[2], a, v1[0], v1[1]);
        mma8(o[3], a, v1[2], v1[3]);
    }
    float* ap = g_att + (size_t)b * 18816 + h * 32;
#pragma unroll
    for (int nj = 0; nj < 4; nj++) {
        int d = nj * 8 + 2 * t;
        if (rA < 49)
            *(float2*)&ap[(size_t)rA * 384 + d] =
                make_float2(tf32f(o[nj][0]), tf32f(o[nj][1]));
        if (rA + 8 < 49)
            *(float2*)&ap[(size_t)(rA + 8) * 384 + d] =
                make_float2(tf32f(o[nj][2]), tf32f(o[nj][3]));
    }
}

// ---------------------------------------------------------------------------
// Launch: 4-chunk software pipeline. GEMMs on the capturing (default) stream,
// attention on a forked stream s1; fork/join via events (captured as edges).
//   qkv(c) -> eq[c] -> attn(c) on s1 -> ea[c] -> out(c)
// ---------------------------------------------------------------------------
extern "C" void kernel_launch(void* const* d_in, const int* in_sizes, int n_in,
                              void* d_out, int out_size)
{
    const float* hidden = (const float*)d_in[0];
    const float* mask   = (const float*)d_in[1];
    const float* w_qkv  = (const float*)d_in[2];
    const float* b_qkv  = (const float*)d_in[3];
    const float* w_out  = (const float*)d_in[4];
    const float* b_out  = (const float*)d_in[5];
    const float* table  = (const float*)d_in[6];
    float* out = (float*)d_out;

    float* hid_p; cudaGetSymbolAddress((void**)&hid_p, g_hid);
    float* wq_p;  cudaGetSymbolAddress((void**)&wq_p,  g_wq);
    float* wo_p;  cudaGetSymbolAddress((void**)&wo_p,  g_wo);

    const int SMEM = 73728;
    cudaFuncSetAttribute(mma_qkv_kernel, cudaFuncAttributeMaxDynamicSharedMemorySize, SMEM);
    cudaFuncSetAttribute(mma_out_kernel, cudaFuncAttributeMaxDynamicSharedMemorySize, SMEM);

    cudaStream_t s1;
    cudaStreamCreateWithFlags(&s1, cudaStreamNonBlocking);
    cudaEvent_t eq[4], ea[4];
    for (int c = 0; c < 4; c++) {
        cudaEventCreateWithFlags(&eq[c], cudaEventDisableTiming);
        cudaEventCreateWithFlags(&ea[c], cudaEventDisableTiming);
    }

    prep_kernel<<<(NH4 + NQ4 + NO4 + 255) / 256, 256>>>(
        (const float4*)hidden, (const float4*)w_qkv, (const float4*)w_out,
        (float4*)hid_p, (float4*)wq_p, (float4*)wo_p);

    // qkv chunks on default stream; record event after each
    for (int c = 0; c < 4; c++) {
        mma_qkv_kernel<<<dim3(9, 392), 256, SMEM>>>(b_qkv, c * 25088);
        cudaEventRecord(eq[c], 0);
    }
    // attention chunks on s1, each gated on its qkv chunk
    for (int c = 0; c < 4; c++) {
        cudaStreamWaitEvent(s1, eq[c], 0);
        attn_kernel<<<6144, 128, 0, s1>>>(mask, table, c * 6144);
        cudaEventRecord(ea[c], s1);
    }
    // out-proj chunks on default stream, each gated on its attn chunk (join)
    for (int c = 0; c < 4; c++) {
        cudaStreamWaitEvent(0, ea[c], 0);
        mma_out_kernel<<<dim3(3, 392), 256, SMEM>>>(b_out, out, c * 25088);
    }
}

// round 17
// speedup vs baseline: 1.0789x; 1.0789x over previous
#include <cuda_runtime.h>
#include <math.h>
#include <stdint.h>

#define NROWS 100352

__device__ float g_q[(size_t)24576*1568];   // [B*H, 49, 32], pre-scaled, tf32-rounded
__device__ float g_k[(size_t)24576*1568];
__device__ float g_v[(size_t)24576*1568];
__device__ float g_att[(size_t)NROWS*384];  // tf32-rounded
__device__ float g_hid[(size_t)NROWS*384];  // tf32-rounded hidden
__device__ float g_wq[1152*384];            // tf32-rounded w_qkv
__device__ float g_wo[384*384];             // tf32-rounded w_out
__device__ int   g_pack[2401];              // (i*60+j)<<16 | ridx*12

__device__ __forceinline__ uint32_t smem_u32(const void* p) {
    uint32_t a;
    asm("{ .reg .u64 t; cvta.to.shared.u64 t, %1; cvt.u32.u64 %0, t; }" : "=r"(a) : "l"(p));
    return a;
}
__device__ __forceinline__ uint32_t f2tf(float x) {
    uint32_t r; asm("cvt.rna.tf32.f32 %0, %1;" : "=r"(r) : "f"(x)); return r;
}
__device__ __forceinline__ float tf32f(float x) { return __uint_as_float(f2tf(x)); }
__device__ __forceinline__ void mma8(float* c, const uint32_t* a, uint32_t b0, uint32_t b1) {
    asm volatile("mma.sync.aligned.m16n8k8.row.col.f32.tf32.tf32.f32 "
        "{%0,%1,%2,%3}, {%4,%5,%6,%7}, {%8,%9}, {%0,%1,%2,%3};"
        : "+f"(c[0]), "+f"(c[1]), "+f"(c[2]), "+f"(c[3])
        : "r"(a[0]), "r"(a[1]), "r"(a[2]), "r"(a[3]), "r"(b0), "r"(b1));
}
__device__ __forceinline__ void ldsm4(uint32_t* r, uint32_t a) {
    asm volatile("ldmatrix.sync.aligned.m8n8.x4.shared.b16 {%0,%1,%2,%3}, [%4];"
        : "=r"(r[0]), "=r"(r[1]), "=r"(r[2]), "=r"(r[3]) : "r"(a));
}
__device__ __forceinline__ void ldsm2(uint32_t* r, uint32_t a) {
    asm volatile("ldmatrix.sync.aligned.m8n8.x2.shared.b16 {%0,%1}, [%2];"
        : "=r"(r[0]), "=r"(r[1]) : "r"(a));
}
__device__ __forceinline__ void cp16(uint32_t s, const float* g) {
    asm volatile("cp.async.cg.shared.global [%0], [%1], 16;" :: "r"(s), "l"(g));
}

// ---------------------------------------------------------------------------
// Single prep kernel: tf32-round hidden / w_qkv / w_out + build pack table.
// ---------------------------------------------------------------------------
#define NH4 9633792   // NROWS*384/4
#define NQ4 110592    // 1152*384/4
#define NO4 36864     // 384*384/4

__global__ void prep_kernel(const float4* __restrict__ hid, const float4* __restrict__ wq,
                            const float4* __restrict__ wo, float4* __restrict__ dh,
                            float4* __restrict__ dwq, float4* __restrict__ dwo)
{
    int i = blockIdx.x * blockDim.x + threadIdx.x;
    const float4* s; float4* d; int k;
    if (i < NH4)            { s = hid; d = dh;  k = i; }
    else if (i < NH4 + NQ4) { s = wq;  d = dwq; k = i - NH4; }
    else if (i < NH4 + NQ4 + NO4) { s = wo; d = dwo; k = i - NH4 - NQ4; }
    else return;
    float4 v = s[k];
    v.x = tf32f(v.x); v.y = tf32f(v.y); v.z = tf32f(v.z); v.w = tf32f(v.w);
    d[k] = v;
    if (i < 2401) {
        int r = i / 49, j = i - r * 49;
        int yi = r / 7, xi = r - yi * 7, yj = j / 7, xj = j - yj * 7;
        int ridx = (yi - yj + 6) * 13 + (xi - xj + 6);
        g_pack[i] = ((r * 60 + j) << 16) | (ridx * 12);
    }
}

// ===========================================================================
// TF32 GEMM: C[64x128] of A[M,384] @ W[N,384]^T; inputs pre-rounded.
// 8 warps (2m x 4n), each 32x32 output (acc 32 regs) -> 3 CTAs/SM.
// (unchanged from R12/R15)
// ===========================================================================
__device__ __forceinline__ void gemm_tf32(const float* __restrict__ A,
                                          const float* __restrict__ W,
                                          int bm, int bn, float acc[2][4][4])
{
    extern __shared__ float sm[];
    const int tid = threadIdx.x;
    const int l = tid & 31, l7 = l & 7;
    const int wm = (tid >> 5) >> 2, wn = (tid >> 5) & 3;

    const int rA0 = tid >> 3, c4 = tid & 7;
    const float* gaA0 = A + (size_t)(bm + rA0) * 384 + c4 * 4;
    const float* gaA1 = gaA0 + (size_t)32 * 384;
    const float* gbB0 = W + (size_t)(bn + rA0) * 384 + c4 * 4;
    const float* gbB1 = gbB0 + (size_t)32 * 384;
    const float* gbB2 = gbB0 + (size_t)64 * 384;
    const float* gbB3 = gbB0 + (size_t)96 * 384;
    const uint32_t smbase = smem_u32(sm);
    const uint32_t sw = (uint32_t)(((c4 ^ rA0) & 7) << 4);
    const uint32_t sAr0 = smbase + (uint32_t)(rA0 * 128) + sw;
    const uint32_t sAr1 = sAr0 + 32 * 128;
    const uint32_t sBr0 = smbase + 24576 + (uint32_t)(rA0 * 128) + sw;
    const uint32_t sBr1 = sBr0 + 32 * 128;
    const uint32_t sBr2 = sBr0 + 64 * 128;
    const uint32_t sBr3 = sBr0 + 96 * 128;

#pragma unroll
    for (int mi = 0; mi < 2; mi++)
#pragma unroll
        for (int nj = 0; nj < 4; nj++)
#pragma unroll
            for (int q = 0; q < 4; q++) acc[mi][nj][q] = 0.f;

#define ISSUE(KT) do {                                                        \
    uint32_t oa = (uint32_t)((KT) % 3) * 8192;                                \
    uint32_t ob = (uint32_t)((KT) % 3) * 16384;                               \
    int ko = (KT) * 32;                                                       \
    cp16(sAr0 + oa, gaA0 + ko);  cp16(sAr1 + oa, gaA1 + ko);                  \
    cp16(sBr0 + ob, gbB0 + ko);  cp16(sBr1 + ob, gbB1 + ko);                  \
    cp16(sBr2 + ob, gbB2 + ko);  cp16(sBr3 + ob, gbB3 + ko);                  \
    asm volatile("cp.async.commit_group;" ::: "memory");                      \
} while (0)

    ISSUE(0); ISSUE(1);

    const int ah = (l >> 3) & 1, bh2 = l >> 4;
    uint32_t a_rb[2], b_rb[2];
#pragma unroll
    for (int mi = 0; mi < 2; mi++)
        a_rb[mi] = (uint32_t)((wm * 32 + mi * 16 + l7 + ah * 8) * 128);
#pragma unroll
    for (int p = 0; p < 2; p++)
        b_rb[p] = (uint32_t)((wn * 32 + p * 16 + l7 + bh2 * 8) * 128);

    for (int kt = 0; kt < 12; kt++) {
        if (kt < 11) asm volatile("cp.async.wait_group 1;" ::: "memory");
        else         asm volatile("cp.async.wait_group 0;" ::: "memory");
        __syncthreads();
        if (kt < 10) ISSUE(kt + 2);

        const uint32_t bA = smbase + (uint32_t)(kt % 3) * 8192;
        const uint32_t bB = smbase + 24576 + (uint32_t)(kt % 3) * 16384;
#pragma unroll
        for (int kc = 0; kc < 4; kc++) {
            const uint32_t uA = (uint32_t)(((2 * kc + bh2) ^ l7) << 4);
            const uint32_t uB = (uint32_t)(((2 * kc + ah) ^ l7) << 4);
            uint32_t af0[4], af1[4], b0[4], b1[4];
            ldsm4(af0, bA + a_rb[0] + uA);
            ldsm4(af1, bA + a_rb[1] + uA);
            ldsm4(b0, bB + b_rb[0] + uB);
            ldsm4(b1, bB + b_rb[1] + uB);
            mma8(acc[0][0], af0, b0[0], b0[1]);
            mma8(acc[0][1], af0, b0[2], b0[3]);
            mma8(acc[0][2], af0, b1[0], b1[1]);
            mma8(acc[0][3], af0, b1[2], b1[3]);
            mma8(acc[1][0], af1, b0[0], b0[1]);
            mma8(acc[1][1], af1, b0[2], b0[3]);
            mma8(acc[1][2], af1, b1[0], b1[1]);
            mma8(acc[1][3], af1, b1[2], b1[3]);
        }
    }
#undef ISSUE
}

// ---------------------------------------------------------------------------
__global__ void __launch_bounds__(256, 3)
mma_qkv_kernel(const float* __restrict__ bias)
{
    int tid = threadIdx.x;
    int bm = blockIdx.y * 64, bn = blockIdx.x * 128;
    float acc[2][4][4];
    gemm_tf32(g_hid, g_wq, bm, bn, acc);

    int l = tid & 31;
    int wm = (tid >> 5) >> 2, wn = (tid >> 5) & 3;
    int part = bn / 384;
    int h = ((bn % 384) + wn * 32) >> 5;
    const float scl = (part == 0) ? 0.17677669529663687f : 1.0f;
    float* base = (part == 0) ? g_q : (part == 1) ? g_k : g_v;

#pragma unroll
    for (int mi = 0; mi < 2; mi++)
#pragma unroll
        for (int nj = 0; nj < 4; nj++) {
            int n = bn + wn * 32 + nj * 8 + (l & 3) * 2;
            int d = nj * 8 + (l & 3) * 2;
            float b0 = bias[n], b1 = bias[n + 1];
#pragma unroll
            for (int rh = 0; rh < 2; rh++) {
                int row = bm + wm * 32 + mi * 16 + (l >> 2) + rh * 8;
                int bb = row / 49, ss = row - bb * 49;
                size_t o = (((size_t)(bb * 12 + h) * 49 + ss) << 5) + d;
                *(float2*)&base[o] =
                    make_float2(tf32f((acc[mi][nj][rh*2] + b0) * scl),
                                tf32f((acc[mi][nj][rh*2+1] + b1) * scl));
            }
        }
}

// ---------------------------------------------------------------------------
__global__ void __launch_bounds__(256, 3)
mma_out_kernel(const float* __restrict__ bias, float* __restrict__ C)
{
    int tid = threadIdx.x;
    int bm = blockIdx.y * 64, bn = blockIdx.x * 128;
    float acc[2][4][4];
    gemm_tf32(g_att, g_wo, bm, bn, acc);

    int l = tid & 31;
    int wm = (tid >> 5) >> 2, wn = (tid >> 5) & 3;
#pragma unroll
    for (int mi = 0; mi < 2; mi++)
#pragma unroll
        for (int nj = 0; nj < 4; nj++) {
            int n = bn + wn * 32 + nj * 8 + (l & 3) * 2;
            float b0 = bias[n], b1 = bias[n + 1];
#pragma unroll
            for (int rh = 0; rh < 2; rh++) {
                int row = bm + wm * 32 + mi * 16 + (l >> 2) + rh * 8;
                *(float2*)&C[(size_t)row * 384 + n] =
                    make_float2(acc[mi][nj][rh*2] + b0, acc[mi][nj][rh*2+1] + b1);
            }
        }
}

// ---------------------------------------------------------------------------
// Attention: one CTA per (b,h). Compact smem (31.5 KB) for higher occupancy:
//   smx layout (floats): qs @0 (56x36=2016), ks @2016 (56x36=2016),
//                        amb @4032 (56x60=3360), pad @7392 (480)
// vt (V transposed, 32x60) OVERLAYS the qs region after the QK phase.
// ldsm reads of padded rows 56..63 spill into the adjacent region/pad
// (in-bounds, garbage, masked at output). Live-data math identical to R15.
// ---------------------------------------------------------------------------
__global__ void __launch_bounds__(128)
attn_kernel(const float* __restrict__ mask, const float* __restrict__ table)
{
    __shared__ float smx[7872];
    float* qs  = smx;           // 56 x 36 (rows 56..63 spill into ks: garbage)
    float* ks  = smx + 2016;    // 56 x 36
    float* amb = smx + 4032;    // 56 x 60 (rows 56..63 spill into pad)
    float* vt  = smx;           // 32 x 60, valid only after QK phase

    int bh = blockIdx.x;
    int b = bh / 12, h = bh - b * 12;
    int tid = threadIdx.x, w = tid >> 5, l = tid & 31, g = l >> 2, t = l & 3;
    const int l7 = l & 7, ah = (l >> 3) & 1, bh2 = l >> 4;

    const float4* qg = (const float4*)(g_q + (size_t)bh * 1568);
    const float4* kg = (const float4*)(g_k + (size_t)bh * 1568);
    const float4* vg = (const float4*)(g_v + (size_t)bh * 1568);
    for (int e = tid; e < 392; e += 128) {
        int i = e >> 3, c = (e & 7) * 4;
        *(float4*)&qs[i * 36 + c] = qg[e];
        *(float4*)&ks[i * 36 + c] = kg[e];
    }
    const float* mrow = mask + (size_t)b * 2401;
    for (int e = tid; e < 2401; e += 128) {
        int pk = g_pack[e];
        amb[pk >> 16] = mrow[e] + table[(pk & 0xFFFF) + h];
    }
    __syncthreads();

    const uint32_t qsb = smem_u32(qs), ksb = smem_u32(ks);
    const uint32_t vtb = smem_u32(vt), ambb = smem_u32(amb);
    const uint32_t qrow = (uint32_t)((w * 16 + l7 + ah * 8) * 144);
    uint32_t krow[3];
#pragma unroll
    for (int p = 0; p < 3; p++)
        krow[p] = (uint32_t)((p * 16 + l7 + bh2 * 8) * 144);
    const uint32_t krow6 = (uint32_t)((48 + l7) * 144);
    uint32_t vrow[2];
#pragma unroll
    for (int p = 0; p < 2; p++)
        vrow[p] = (uint32_t)((p * 16 + l7 + bh2 * 8) * 240);

    // QK^T
    float s[7][4];
#pragma unroll
    for (int T = 0; T < 7; T++) { s[T][0]=0.f; s[T][1]=0.f; s[T][2]=0.f; s[T][3]=0.f; }
    const int rA = w * 16 + g;
#pragma unroll
    for (int kc = 0; kc < 4; kc++) {
        uint32_t a[4];
        ldsm4(a, qsb + qrow + (uint32_t)((2 * kc + bh2) << 4));
        uint32_t uB = (uint32_t)((2 * kc + ah) << 4);
#pragma unroll
        for (int p = 0; p < 3; p++) {
            uint32_t kb[4];
            ldsm4(kb, ksb + krow[p] + uB);
            mma8(s[2*p],   a, kb[0], kb[1]);
            mma8(s[2*p+1], a, kb[2], kb[3]);
        }
        uint32_t k2[2];
        ldsm2(k2, ksb + krow6 + uB);
        mma8(s[6], a, k2[0], k2[1]);
    }
    // all warps done reading qs -> safe to overwrite with vt
    __syncthreads();

    // load V transposed into vt (qs region); latency hides under softmax
    for (int e = tid; e < 224; e += 128) {
        int d = e & 31, jz = 49 + (e >> 5);
        vt[d * 60 + jz] = 0.f;
    }
    for (int e = tid; e < 392; e += 128) {
        int i = e >> 3, c = (e & 7) * 4;
        float4 vv = vg[e];
        vt[(c + 0) * 60 + i] = vv.x;
        vt[(c + 1) * 60 + i] = vv.y;
        vt[(c + 2) * 60 + i] = vv.z;
        vt[(c + 3) * 60 + i] = vv.w;
    }

    // + bias + mask, j>=49 -> -inf
#pragma unroll
    for (int T = 0; T < 7; T++) {
        int j0 = T * 8 + 2 * t;
        float2 m0 = *(const float2*)&amb[rA * 60 + j0];
        float2 m1 = *(const float2*)&amb[(rA + 8) * 60 + j0];
        s[T][0] = (j0 < 49)     ? s[T][0] + m0.x : -1e30f;
        s[T][1] = (j0 + 1 < 49) ? s[T][1] + m0.y : -1e30f;
        s[T][2] = (j0 < 49)     ? s[T][2] + m1.x : -1e30f;
        s[T][3] = (j0 + 1 < 49) ? s[T][3] + m1.y : -1e30f;
    }
    // softmax (rows rA, rA+8)
    float mA = -1e30f, mB = -1e30f;
#pragma unroll
    for (int T = 0; T < 7; T++) {
        mA = fmaxf(mA, fmaxf(s[T][0], s[T][1]));
        mB = fmaxf(mB, fmaxf(s[T][2], s[T][3]));
    }
    mA = fmaxf(mA, __shfl_xor_sync(~0u, mA, 1)); mA = fmaxf(mA, __shfl_xor_sync(~0u, mA, 2));
    mB = fmaxf(mB, __shfl_xor_sync(~0u, mB, 1)); mB = fmaxf(mB, __shfl_xor_sync(~0u, mB, 2));
    float dA = 0.f, dB = 0.f;
#pragma unroll
    for (int T = 0; T < 7; T++) {
        s[T][0] = __expf(s[T][0] - mA); s[T][1] = __expf(s[T][1] - mA);
        s[T][2] = __expf(s[T][2] - mB); s[T][3] = __expf(s[T][3] - mB);
        dA += s[T][0] + s[T][1]; dB += s[T][2] + s[T][3];
    }
    dA += __shfl_xor_sync(~0u, dA, 1); dA += __shfl_xor_sync(~0u, dA, 2);
    dB += __shfl_xor_sync(~0u, dB, 1); dB += __shfl_xor_sync(~0u, dB, 2);
    float iA = 1.f / dA, iB = 1.f / dB;
#pragma unroll
    for (int T = 0; T < 7; T++) {
        int j0 = T * 8 + 2 * t;
        *(float2*)&amb[rA * 60 + j0] =
            make_float2(tf32f(s[T][0] * iA), tf32f(s[T][1] * iA));
        if (rA + 8 < 56)
            *(float2*)&amb[(rA + 8) * 60 + j0] =
                make_float2(tf32f(s[T][2] * iB), tf32f(s[T][3] * iB));
    }
    // vt writes (cross-thread) + P stores must be visible before PV
    __syncthreads();

    // PV: P and V fragments both via ldmatrix
    const uint32_t prow = (uint32_t)((w * 16 + l7 + ah * 8) * 240);
    float o[4][4];
#pragma unroll
    for (int nj = 0; nj < 4; nj++) { o[nj][0]=0.f; o[nj][1]=0.f; o[nj][2]=0.f; o[nj][3]=0.f; }
#pragma unroll
    for (int kc = 0; kc < 7; kc++) {
        uint32_t a[4];
        ldsm4(a, ambb + prow + (uint32_t)((2 * kc + bh2) << 4));
        uint32_t uV = (uint32_t)((2 * kc + ah) << 4);
        uint32_t v0[4], v1[4];
        ldsm4(v0, vtb + vrow[0] + uV);
        ldsm4(v1, vtb + vrow[1] + uV);
        mma8(o[0], a, v0[0], v0[1]);
        mma8(o[1], a, v0[2], v0[3]);
        mma8(o[2], a, v1[0], v1[1]);
        mma8(o[3], a, v1[2], v1[3]);
    }
    float* ap = g_att + (size_t)b * 18816 + h * 32;
#pragma unroll
    for (int nj = 0; nj < 4; nj++) {
        int d = nj * 8 + 2 * t;
        if (rA < 49)
            *(float2*)&ap[(size_t)rA * 384 + d] =
                make_float2(tf32f(o[nj][0]), tf32f(o[nj][1]));
        if (rA + 8 < 49)
            *(float2*)&ap[(size_t)(rA + 8) * 384 + d] =
                make_float2(tf32f(o[nj][2]), tf32f(o[nj][3]));
    }
}

// ---------------------------------------------------------------------------
extern "C" void kernel_launch(void* const* d_in, const int* in_sizes, int n_in,
                              void* d_out, int out_size)
{
    const float* hidden = (const float*)d_in[0];
    const float* mask   = (const float*)d_in[1];
    const float* w_qkv  = (const float*)d_in[2];
    const float* b_qkv  = (const float*)d_in[3];
    const float* w_out  = (const float*)d_in[4];
    const float* b_out  = (const float*)d_in[5];
    const float* table  = (const float*)d_in[6];
    float* out = (float*)d_out;

    float* hid_p; cudaGetSymbolAddress((void**)&hid_p, g_hid);
    float* wq_p;  cudaGetSymbolAddress((void**)&wq_p,  g_wq);
    float* wo_p;  cudaGetSymbolAddress((void**)&wo_p,  g_wo);

    prep_kernel<<<(NH4 + NQ4 + NO4 + 255) / 256, 256>>>(
        (const float4*)hidden, (const float4*)w_qkv, (const float4*)w_out,
        (float4*)hid_p, (float4*)wq_p, (float4*)wo_p);

    const int SMEM = 73728;
    cudaFuncSetAttribute(mma_qkv_kernel, cudaFuncAttributeMaxDynamicSharedMemorySize, SMEM);
    cudaFuncSetAttribute(mma_out_kernel, cudaFuncAttributeMaxDynamicSharedMemorySize, SMEM);

    mma_qkv_kernel<<<dim3(9, 1568), 256, SMEM>>>(b_qkv);
    attn_kernel<<<24576, 128>>>(mask, table);
    mma_out_kernel<<<dim3(3, 1568), 256, SMEM>>>(b_out, out);
}